// round 2
// baseline (speedup 1.0000x reference)
#include <cuda_runtime.h>

#define NN 100000
#define EE 1600000
#define D  64

// Scratch (device globals: allocation-free per harness rules)
__device__ float g_agg[(size_t)NN * D];   // 25.6 MB
__device__ float g_deg[NN];

// ---------------------------------------------------------------------------
// Kernel 1: zero the scratch accumulators
// ---------------------------------------------------------------------------
__global__ void zero_kernel() {
    int i = blockIdx.x * blockDim.x + threadIdx.x;
    if (i < NN * D) g_agg[i] = 0.0f;
    if (i < NN)     g_deg[i] = 0.0f;
}

// ---------------------------------------------------------------------------
// Kernel 2: scatter-add of x[src] into agg[dst], 16 threads per edge
// (each thread handles one float4 chunk of the 64-float row).
// edge_index is int32 (JAX default x64-disabled downcasts int64 -> int32).
// Vectorized global reduction: red.global.add.v4.f32 (sm_90+).
// ---------------------------------------------------------------------------
__global__ void scatter_kernel(const float* __restrict__ x,
                               const int* __restrict__ ei) {
    long long tid = (long long)blockIdx.x * blockDim.x + threadIdx.x;
    if (tid >= (long long)EE * 16) return;
    int e = (int)(tid >> 4);
    int c = (int)(tid & 15);

    int dst = ei[e];        // row 0: destination
    int src = ei[EE + e];   // row 1: source

    float4 v = ((const float4*)x)[(long long)src * 16 + c];
    float4* p = (float4*)(g_agg + (long long)dst * D + c * 4);
    asm volatile("red.global.add.v4.f32 [%0], {%1, %2, %3, %4};"
                 :: "l"(p), "f"(v.x), "f"(v.y), "f"(v.z), "f"(v.w)
                 : "memory");
    if (c == 0) atomicAdd(g_deg + dst, 1.0f);
}

// ---------------------------------------------------------------------------
// Kernel 3: per-node finalize:
//   h = [x[n], agg[n]/max(deg,1)]  (128)
//   out = LayerNorm(relu(h @ W^T + b)) * gamma + beta
// One node per thread; W (64x128 = 32KB) staged in shared memory, broadcast
// LDS.128 reads; 64 fp32 accumulators in registers.
// ---------------------------------------------------------------------------
__global__ void __launch_bounds__(256)
finalize_kernel(const float* __restrict__ x,
                const float* __restrict__ W,
                const float* __restrict__ b,
                const float* __restrict__ gamma,
                const float* __restrict__ beta,
                float* __restrict__ out) {
    __shared__ float Wsh[D * 2 * D];           // [64][128] row-major, 32 KB
    __shared__ float bsh[D], gsh[D], besh[D];

    for (int i = threadIdx.x; i < D * 2 * D; i += blockDim.x) Wsh[i] = W[i];
    if (threadIdx.x < D) {
        bsh[threadIdx.x]  = b[threadIdx.x];
        gsh[threadIdx.x]  = gamma[threadIdx.x];
        besh[threadIdx.x] = beta[threadIdx.x];
    }
    __syncthreads();

    int node = blockIdx.x * blockDim.x + threadIdx.x;
    if (node >= NN) return;

    float acc[D];
#pragma unroll
    for (int d = 0; d < D; d++) acc[d] = bsh[d];

    // First half: x part (W columns [0,64))
    const float4* xr = (const float4*)(x + (long long)node * D);
#pragma unroll 1
    for (int k4 = 0; k4 < 16; k4++) {
        float4 h = xr[k4];
#pragma unroll
        for (int d = 0; d < D; d++) {
            float4 w = *(const float4*)(Wsh + d * 128 + k4 * 4);
            acc[d] += h.x * w.x + h.y * w.y + h.z * w.z + h.w * w.w;
        }
    }

    // Second half: mean-aggregated part (W columns [64,128))
    float invdeg = 1.0f / fmaxf(g_deg[node], 1.0f);
    const float4* ar = (const float4*)(g_agg + (long long)node * D);
#pragma unroll 1
    for (int k4 = 0; k4 < 16; k4++) {
        float4 h = ar[k4];
        h.x *= invdeg; h.y *= invdeg; h.z *= invdeg; h.w *= invdeg;
#pragma unroll
        for (int d = 0; d < D; d++) {
            float4 w = *(const float4*)(Wsh + d * 128 + 64 + k4 * 4);
            acc[d] += h.x * w.x + h.y * w.y + h.z * w.z + h.w * w.w;
        }
    }

    // ReLU + LayerNorm (population variance) entirely in registers
    float sum = 0.0f;
#pragma unroll
    for (int d = 0; d < D; d++) { acc[d] = fmaxf(acc[d], 0.0f); sum += acc[d]; }
    float mu = sum * (1.0f / D);
    float var = 0.0f;
#pragma unroll
    for (int d = 0; d < D; d++) { float t = acc[d] - mu; var += t * t; }
    float rstd = rsqrtf(var * (1.0f / D) + 1e-5f);

    float4* orow = (float4*)(out + (long long)node * D);
#pragma unroll 1
    for (int k4 = 0; k4 < 16; k4++) {
        float4 o;
        o.x = (acc[k4 * 4 + 0] - mu) * rstd * gsh[k4 * 4 + 0] + besh[k4 * 4 + 0];
        o.y = (acc[k4 * 4 + 1] - mu) * rstd * gsh[k4 * 4 + 1] + besh[k4 * 4 + 1];
        o.z = (acc[k4 * 4 + 2] - mu) * rstd * gsh[k4 * 4 + 2] + besh[k4 * 4 + 2];
        o.w = (acc[k4 * 4 + 3] - mu) * rstd * gsh[k4 * 4 + 3] + besh[k4 * 4 + 3];
        orow[k4] = o;
    }
}

// ---------------------------------------------------------------------------
extern "C" void kernel_launch(void* const* d_in, const int* in_sizes, int n_in,
                              void* d_out, int out_size) {
    const float* x     = (const float*)d_in[0];
    const int*   ei    = (const int*)d_in[1];
    const float* W     = (const float*)d_in[2];
    const float* b     = (const float*)d_in[3];
    const float* gamma = (const float*)d_in[4];
    const float* beta  = (const float*)d_in[5];
    float*       out   = (float*)d_out;

    (void)in_sizes; (void)n_in; (void)out_size;

    zero_kernel<<<(NN * D + 255) / 256, 256>>>();

    long long scatter_threads = (long long)EE * 16;
    scatter_kernel<<<(unsigned)((scatter_threads + 255) / 256), 256>>>(x, ei);

    finalize_kernel<<<(NN + 255) / 256, 256>>>(x, W, b, gamma, beta, out);
}

// round 3
// speedup vs baseline: 1.2237x; 1.2237x over previous
#include <cuda_runtime.h>

#define NN 100000
#define EE 1600000
#define D  64
#define MAXDEG 64   // avg degree = 16; P(deg > 64) ~ e^-126, plus runtime clamp

// Scratch (device globals: allocation-free per harness rules)
__device__ int   g_cnt[NN];                        // per-node degree / fill cursor
__device__ int   g_csr[(size_t)NN * MAXDEG];       // padded CSR of src ids (25.6 MB)
__device__ float g_agg[(size_t)NN * D];            // mean-aggregated features (25.6 MB)

// ---------------------------------------------------------------------------
// Kernel 1: zero the per-node counters (0.4 MB only)
// ---------------------------------------------------------------------------
__global__ void zero_cnt_kernel() {
    int i = blockIdx.x * blockDim.x + threadIdx.x;
    if (i < NN) g_cnt[i] = 0;
}

// ---------------------------------------------------------------------------
// Kernel 2: bucket edges into padded CSR. One int atomicAdd per edge.
// ---------------------------------------------------------------------------
__global__ void fill_kernel(const int* __restrict__ ei) {
    int e = blockIdx.x * blockDim.x + threadIdx.x;
    if (e >= EE) return;
    int dst = ei[e];        // row 0: destination
    int src = ei[EE + e];   // row 1: source
    int pos = atomicAdd(g_cnt + dst, 1);
    if (pos < MAXDEG) g_csr[(size_t)dst * MAXDEG + pos] = src;
}

// ---------------------------------------------------------------------------
// Kernel 3: warp-per-node deterministic mean aggregation.
// Lane t owns floats [2t, 2t+1] of the 64-float row -> every neighbor row
// read is one fully-coalesced 256B warp transaction. 4 neighbors in flight
// per iteration (broadcast int4 CSR read) for memory-level parallelism.
// ---------------------------------------------------------------------------
__global__ void __launch_bounds__(256)
aggregate_kernel(const float* __restrict__ x) {
    int warp = (blockIdx.x * blockDim.x + threadIdx.x) >> 5;
    int lane = threadIdx.x & 31;
    if (warp >= NN) return;
    const int node = warp;

    int cnt = g_cnt[node];
    int n = min(cnt, MAXDEG);

    float sx = 0.0f, sy = 0.0f;
    const int4* csr4 = (const int4*)(g_csr + (size_t)node * MAXDEG);

    int i = 0;
    for (; i + 4 <= n; i += 4) {
        int4 s4 = csr4[i >> 2];   // broadcast load (all lanes same address)
        float2 v0 = *(const float2*)(x + (size_t)s4.x * D + 2 * lane);
        float2 v1 = *(const float2*)(x + (size_t)s4.y * D + 2 * lane);
        float2 v2 = *(const float2*)(x + (size_t)s4.z * D + 2 * lane);
        float2 v3 = *(const float2*)(x + (size_t)s4.w * D + 2 * lane);
        sx += (v0.x + v1.x) + (v2.x + v3.x);
        sy += (v0.y + v1.y) + (v2.y + v3.y);
    }
    for (; i < n; i++) {
        int src = g_csr[(size_t)node * MAXDEG + i];
        float2 v = *(const float2*)(x + (size_t)src * D + 2 * lane);
        sx += v.x; sy += v.y;
    }

    float inv = 1.0f / fmaxf((float)cnt, 1.0f);
    *(float2*)(g_agg + (size_t)node * D + 2 * lane) = make_float2(sx * inv, sy * inv);
}

// ---------------------------------------------------------------------------
// Kernel 4: per-node finalize:
//   h = [x[n], g_agg[n]]  (128)  (g_agg already holds the mean)
//   out = LayerNorm(relu(h @ W^T + b)) * gamma + beta
// One node per thread; W (64x128 = 32KB) staged in shared memory, broadcast
// LDS.128 reads; 64 fp32 accumulators in registers.
// ---------------------------------------------------------------------------
__global__ void __launch_bounds__(256)
finalize_kernel(const float* __restrict__ x,
                const float* __restrict__ W,
                const float* __restrict__ b,
                const float* __restrict__ gamma,
                const float* __restrict__ beta,
                float* __restrict__ out) {
    __shared__ float Wsh[D * 2 * D];           // [64][128] row-major, 32 KB
    __shared__ float bsh[D], gsh[D], besh[D];

    for (int i = threadIdx.x; i < D * 2 * D; i += blockDim.x) Wsh[i] = W[i];
    if (threadIdx.x < D) {
        bsh[threadIdx.x]  = b[threadIdx.x];
        gsh[threadIdx.x]  = gamma[threadIdx.x];
        besh[threadIdx.x] = beta[threadIdx.x];
    }
    __syncthreads();

    int node = blockIdx.x * blockDim.x + threadIdx.x;
    if (node >= NN) return;

    float acc[D];
#pragma unroll
    for (int d = 0; d < D; d++) acc[d] = bsh[d];

    // First half: x part (W columns [0,64))
    const float4* xr = (const float4*)(x + (long long)node * D);
#pragma unroll 1
    for (int k4 = 0; k4 < 16; k4++) {
        float4 h = xr[k4];
#pragma unroll
        for (int d = 0; d < D; d++) {
            float4 w = *(const float4*)(Wsh + d * 128 + k4 * 4);
            acc[d] += h.x * w.x + h.y * w.y + h.z * w.z + h.w * w.w;
        }
    }

    // Second half: mean-aggregated part (W columns [64,128))
    const float4* ar = (const float4*)(g_agg + (long long)node * D);
#pragma unroll 1
    for (int k4 = 0; k4 < 16; k4++) {
        float4 h = ar[k4];
#pragma unroll
        for (int d = 0; d < D; d++) {
            float4 w = *(const float4*)(Wsh + d * 128 + 64 + k4 * 4);
            acc[d] += h.x * w.x + h.y * w.y + h.z * w.z + h.w * w.w;
        }
    }

    // ReLU + LayerNorm (population variance) entirely in registers
    float sum = 0.0f;
#pragma unroll
    for (int d = 0; d < D; d++) { acc[d] = fmaxf(acc[d], 0.0f); sum += acc[d]; }
    float mu = sum * (1.0f / D);
    float var = 0.0f;
#pragma unroll
    for (int d = 0; d < D; d++) { float t = acc[d] - mu; var += t * t; }
    float rstd = rsqrtf(var * (1.0f / D) + 1e-5f);

    float4* orow = (float4*)(out + (long long)node * D);
#pragma unroll 1
    for (int k4 = 0; k4 < 16; k4++) {
        float4 o;
        o.x = (acc[k4 * 4 + 0] - mu) * rstd * gsh[k4 * 4 + 0] + besh[k4 * 4 + 0];
        o.y = (acc[k4 * 4 + 1] - mu) * rstd * gsh[k4 * 4 + 1] + besh[k4 * 4 + 1];
        o.z = (acc[k4 * 4 + 2] - mu) * rstd * gsh[k4 * 4 + 2] + besh[k4 * 4 + 2];
        o.w = (acc[k4 * 4 + 3] - mu) * rstd * gsh[k4 * 4 + 3] + besh[k4 * 4 + 3];
        orow[k4] = o;
    }
}

// ---------------------------------------------------------------------------
extern "C" void kernel_launch(void* const* d_in, const int* in_sizes, int n_in,
                              void* d_out, int out_size) {
    const float* x     = (const float*)d_in[0];
    const int*   ei    = (const int*)d_in[1];
    const float* W     = (const float*)d_in[2];
    const float* b     = (const float*)d_in[3];
    const float* gamma = (const float*)d_in[4];
    const float* beta  = (const float*)d_in[5];
    float*       out   = (float*)d_out;

    (void)in_sizes; (void)n_in; (void)out_size;

    zero_cnt_kernel<<<(NN + 255) / 256, 256>>>();
    fill_kernel<<<(EE + 255) / 256, 256>>>(ei);
    aggregate_kernel<<<(NN * 32 + 255) / 256, 256>>>(x);   // warp per node
    finalize_kernel<<<(NN + 255) / 256, 256>>>(x, W, b, gamma, beta, out);
}

// round 4
// speedup vs baseline: 1.8015x; 1.4722x over previous
#include <cuda_runtime.h>

#define NN 100000
#define EE 1600000
#define D  64
#define MAXDEG 64   // avg degree = 16; P(deg > 64) ~ e^-126, plus runtime clamp

#define TM 128              // nodes per block in finalize
#define HPAD 132            // padded row stride for h tile (bank-conflict relief)

// Scratch (device globals: allocation-free per harness rules)
__device__ int   g_cnt[NN];
__device__ int   g_csr[(size_t)NN * MAXDEG];
__device__ float g_agg[(size_t)NN * D];

// ---------------------------------------------------------------------------
// packed f32x2 helpers (Blackwell FFMA2 path)
// ---------------------------------------------------------------------------
__device__ __forceinline__ unsigned long long pk2(float lo, float hi) {
    unsigned long long r;
    asm("mov.b64 %0, {%1, %2};" : "=l"(r) : "f"(lo), "f"(hi));
    return r;
}
__device__ __forceinline__ unsigned long long dup2(float v) {
    unsigned long long r;
    asm("mov.b64 %0, {%1, %1};" : "=l"(r) : "f"(v));
    return r;
}
__device__ __forceinline__ unsigned long long fma2(unsigned long long a,
                                                   unsigned long long b,
                                                   unsigned long long c) {
    unsigned long long d;
    asm("fma.rn.f32x2 %0, %1, %2, %3;" : "=l"(d) : "l"(a), "l"(b), "l"(c));
    return d;
}
__device__ __forceinline__ void unpk2(unsigned long long v, float& lo, float& hi) {
    asm("mov.b64 {%0, %1}, %2;" : "=f"(lo), "=f"(hi) : "l"(v));
}

// ---------------------------------------------------------------------------
// Kernel 1: zero the per-node counters
// ---------------------------------------------------------------------------
__global__ void zero_cnt_kernel() {
    int i = blockIdx.x * blockDim.x + threadIdx.x;
    if (i < NN) g_cnt[i] = 0;
}

// ---------------------------------------------------------------------------
// Kernel 2: bucket edges into padded CSR. One int atomicAdd per edge.
// ---------------------------------------------------------------------------
__global__ void fill_kernel(const int* __restrict__ ei) {
    int e = blockIdx.x * blockDim.x + threadIdx.x;
    if (e >= EE) return;
    int dst = ei[e];        // row 0: destination
    int src = ei[EE + e];   // row 1: source
    int pos = atomicAdd(g_cnt + dst, 1);
    if (pos < MAXDEG) g_csr[(size_t)dst * MAXDEG + pos] = src;
}

// ---------------------------------------------------------------------------
// Kernel 3: warp-per-node deterministic mean aggregation.
// Lane t owns floats [2t, 2t+1]; 8 neighbors in flight per iteration.
// ---------------------------------------------------------------------------
__global__ void __launch_bounds__(256)
aggregate_kernel(const float* __restrict__ x) {
    int warp = (blockIdx.x * blockDim.x + threadIdx.x) >> 5;
    int lane = threadIdx.x & 31;
    if (warp >= NN) return;
    const int node = warp;

    int cnt = g_cnt[node];
    int n = min(cnt, MAXDEG);

    float sx = 0.0f, sy = 0.0f;
    const int4* csr4 = (const int4*)(g_csr + (size_t)node * MAXDEG);

    int i = 0;
    for (; i + 8 <= n; i += 8) {
        int4 a = csr4[(i >> 2) + 0];
        int4 c = csr4[(i >> 2) + 1];
        float2 v0 = *(const float2*)(x + (size_t)a.x * D + 2 * lane);
        float2 v1 = *(const float2*)(x + (size_t)a.y * D + 2 * lane);
        float2 v2 = *(const float2*)(x + (size_t)a.z * D + 2 * lane);
        float2 v3 = *(const float2*)(x + (size_t)a.w * D + 2 * lane);
        float2 v4 = *(const float2*)(x + (size_t)c.x * D + 2 * lane);
        float2 v5 = *(const float2*)(x + (size_t)c.y * D + 2 * lane);
        float2 v6 = *(const float2*)(x + (size_t)c.z * D + 2 * lane);
        float2 v7 = *(const float2*)(x + (size_t)c.w * D + 2 * lane);
        sx += ((v0.x + v1.x) + (v2.x + v3.x)) + ((v4.x + v5.x) + (v6.x + v7.x));
        sy += ((v0.y + v1.y) + (v2.y + v3.y)) + ((v4.y + v5.y) + (v6.y + v7.y));
    }
    for (; i < n; i++) {
        int src = g_csr[(size_t)node * MAXDEG + i];
        float2 v = *(const float2*)(x + (size_t)src * D + 2 * lane);
        sx += v.x; sy += v.y;
    }

    float inv = 1.0f / fmaxf((float)cnt, 1.0f);
    *(float2*)(g_agg + (size_t)node * D + 2 * lane) = make_float2(sx * inv, sy * inv);
}

// ---------------------------------------------------------------------------
// Kernel 4: register-tiled fused GEMM + ReLU + LayerNorm.
// Block = 128 nodes. Shared: h tile [128][132] + W^T [128][64].
// Thread tile: 4 nodes x 8 outputs, fp32x2 packed FMA accumulators.
// LN via 8-lane shfl groups (the 8 threads that share a node quad).
// ---------------------------------------------------------------------------
__global__ void __launch_bounds__(256, 2)
finalize_kernel(const float* __restrict__ x,
                const float* __restrict__ W,
                const float* __restrict__ b,
                const float* __restrict__ gamma,
                const float* __restrict__ beta,
                float* __restrict__ out) {
    extern __shared__ float sm[];
    float* hsh = sm;                 // [TM][HPAD]
    float* wt  = sm + TM * HPAD;     // [128][64]  (W transposed: wt[k][d])

    const int tid = threadIdx.x;
    const int bnode0 = blockIdx.x * TM;

    // --- stage h = [x | agg] : 128 nodes x 32 float4 chunks, coalesced ---
    for (int t = tid; t < TM * 32; t += 256) {
        int node = t >> 5;
        int c = t & 31;
        int gnode = min(bnode0 + node, NN - 1);
        float4 v;
        if (c < 16) v = ((const float4*)(x + (size_t)gnode * D))[c];
        else        v = ((const float4*)(g_agg + (size_t)gnode * D))[c - 16];
        *(float4*)&hsh[node * HPAD + c * 4] = v;
    }
    // --- stage W^T: conflict-free STS, strided LDG (W hot in L2) ---
    for (int t = tid; t < 64 * 32; t += 256) {
        int d  = t & 63;
        int kc = t >> 6;
        float4 v = ((const float4*)(W + d * 128))[kc];
        wt[(kc * 4 + 0) * 64 + d] = v.x;
        wt[(kc * 4 + 1) * 64 + d] = v.y;
        wt[(kc * 4 + 2) * 64 + d] = v.z;
        wt[(kc * 4 + 3) * 64 + d] = v.w;
    }
    __syncthreads();

    const int outq  = tid & 7;        // 8 output groups
    const int nodeq = tid >> 3;       // 32 node quads
    const int n0    = nodeq * 4;      // local node base
    const int ocol  = outq * 8;       // output column base

    // bias pairs (same for all 4 nodes)
    unsigned long long bp[4];
    {
        float4 b0 = *(const float4*)(b + ocol);
        float4 b1 = *(const float4*)(b + ocol + 4);
        bp[0] = pk2(b0.x, b0.y); bp[1] = pk2(b0.z, b0.w);
        bp[2] = pk2(b1.x, b1.y); bp[3] = pk2(b1.z, b1.w);
    }
    unsigned long long acc[16];
#pragma unroll
    for (int n = 0; n < 4; n++)
#pragma unroll
        for (int p = 0; p < 4; p++) acc[n * 4 + p] = bp[p];

    unsigned int waddr = (unsigned int)__cvta_generic_to_shared(wt) + ocol * 4u;

    // --- main loop: 128 k-steps, 32 FMAs per step in 16 FFMA2 ---
#pragma unroll 4
    for (int k = 0; k < 2 * D; k++) {
        unsigned long long w0, w1, w2, w3;
        asm volatile("ld.shared.v2.b64 {%0, %1}, [%2];"
                     : "=l"(w0), "=l"(w1) : "r"(waddr + k * 256u));
        asm volatile("ld.shared.v2.b64 {%0, %1}, [%2];"
                     : "=l"(w2), "=l"(w3) : "r"(waddr + k * 256u + 16u));
        unsigned long long h0 = dup2(hsh[(n0 + 0) * HPAD + k]);
        unsigned long long h1 = dup2(hsh[(n0 + 1) * HPAD + k]);
        unsigned long long h2 = dup2(hsh[(n0 + 2) * HPAD + k]);
        unsigned long long h3 = dup2(hsh[(n0 + 3) * HPAD + k]);
        acc[0]  = fma2(h0, w0, acc[0]);  acc[1]  = fma2(h0, w1, acc[1]);
        acc[2]  = fma2(h0, w2, acc[2]);  acc[3]  = fma2(h0, w3, acc[3]);
        acc[4]  = fma2(h1, w0, acc[4]);  acc[5]  = fma2(h1, w1, acc[5]);
        acc[6]  = fma2(h1, w2, acc[6]);  acc[7]  = fma2(h1, w3, acc[7]);
        acc[8]  = fma2(h2, w0, acc[8]);  acc[9]  = fma2(h2, w1, acc[9]);
        acc[10] = fma2(h2, w2, acc[10]); acc[11] = fma2(h2, w3, acc[11]);
        acc[12] = fma2(h3, w0, acc[12]); acc[13] = fma2(h3, w1, acc[13]);
        acc[14] = fma2(h3, w2, acc[14]); acc[15] = fma2(h3, w3, acc[15]);
    }

    // gamma/beta for this thread's 8 output columns
    float4 ga0 = *(const float4*)(gamma + ocol);
    float4 ga1 = *(const float4*)(gamma + ocol + 4);
    float4 be0 = *(const float4*)(beta + ocol);
    float4 be1 = *(const float4*)(beta + ocol + 4);

    // --- per-node ReLU + LayerNorm via 8-lane shfl groups ---
#pragma unroll
    for (int n = 0; n < 4; n++) {
        float v[8];
#pragma unroll
        for (int p = 0; p < 4; p++) unpk2(acc[n * 4 + p], v[2 * p], v[2 * p + 1]);
#pragma unroll
        for (int j = 0; j < 8; j++) v[j] = fmaxf(v[j], 0.0f);

        float s = ((v[0] + v[1]) + (v[2] + v[3])) + ((v[4] + v[5]) + (v[6] + v[7]));
#pragma unroll
        for (int m = 1; m < 8; m <<= 1) s += __shfl_xor_sync(0xffffffffu, s, m);
        float mu = s * (1.0f / D);

        float ss = 0.0f;
#pragma unroll
        for (int j = 0; j < 8; j++) { float t = v[j] - mu; ss += t * t; }
#pragma unroll
        for (int m = 1; m < 8; m <<= 1) ss += __shfl_xor_sync(0xffffffffu, ss, m);
        float rstd = rsqrtf(ss * (1.0f / D) + 1e-5f);

        int gnode = bnode0 + n0 + n;
        if (gnode < NN) {
            float4 o0, o1;
            o0.x = (v[0] - mu) * rstd * ga0.x + be0.x;
            o0.y = (v[1] - mu) * rstd * ga0.y + be0.y;
            o0.z = (v[2] - mu) * rstd * ga0.z + be0.z;
            o0.w = (v[3] - mu) * rstd * ga0.w + be0.w;
            o1.x = (v[4] - mu) * rstd * ga1.x + be1.x;
            o1.y = (v[5] - mu) * rstd * ga1.y + be1.y;
            o1.z = (v[6] - mu) * rstd * ga1.z + be1.z;
            o1.w = (v[7] - mu) * rstd * ga1.w + be1.w;
            float4* orow = (float4*)(out + (size_t)gnode * D + ocol);
            orow[0] = o0;
            orow[1] = o1;
        }
    }
}

// ---------------------------------------------------------------------------
extern "C" void kernel_launch(void* const* d_in, const int* in_sizes, int n_in,
                              void* d_out, int out_size) {
    const float* x     = (const float*)d_in[0];
    const int*   ei    = (const int*)d_in[1];
    const float* W     = (const float*)d_in[2];
    const float* b     = (const float*)d_in[3];
    const float* gamma = (const float*)d_in[4];
    const float* beta  = (const float*)d_in[5];
    float*       out   = (float*)d_out;

    (void)in_sizes; (void)n_in; (void)out_size;

    const int smem_bytes = (TM * HPAD + 128 * 64) * sizeof(float);  // ~100 KB
    cudaFuncSetAttribute(finalize_kernel,
                         cudaFuncAttributeMaxDynamicSharedMemorySize, smem_bytes);

    zero_cnt_kernel<<<(NN + 255) / 256, 256>>>();
    fill_kernel<<<(EE + 255) / 256, 256>>>(ei);
    aggregate_kernel<<<(NN * 32 + 255) / 256, 256>>>(x);   // warp per node
    finalize_kernel<<<(NN + TM - 1) / TM, 256, smem_bytes>>>(x, W, b, gamma, beta, out);
}

// round 6
// speedup vs baseline: 1.9152x; 1.0631x over previous
#include <cuda_runtime.h>
#include <cstdint>

#define NN 100000
#define EE 1600000
#define D  64
#define MAXDEG 64   // avg degree = 16; P(deg > 64) ~ e^-126, plus runtime clamp
#define TM 64       // nodes per finalize CTA
#define HPAD 132    // padded row stride (floats) — conflict-free frag loads

// Scratch (device globals: allocation-free per harness rules)
__device__ int   g_cnt[NN];
__device__ int   g_csr[(size_t)NN * MAXDEG];
__device__ float g_agg[(size_t)NN * D];

// ---------------------------------------------------------------------------
// Kernel 1: zero the per-node counters
// ---------------------------------------------------------------------------
__global__ void zero_cnt_kernel() {
    int i = blockIdx.x * blockDim.x + threadIdx.x;
    if (i < NN) g_cnt[i] = 0;
}

// ---------------------------------------------------------------------------
// Kernel 2: bucket edges into padded CSR. One int atomicAdd per edge.
// ---------------------------------------------------------------------------
__global__ void fill_kernel(const int* __restrict__ ei) {
    int e = blockIdx.x * blockDim.x + threadIdx.x;
    if (e >= EE) return;
    int dst = ei[e];
    int src = ei[EE + e];
    int pos = atomicAdd(g_cnt + dst, 1);
    if (pos < MAXDEG) g_csr[(size_t)dst * MAXDEG + pos] = src;
}

// ---------------------------------------------------------------------------
// Kernel 3: warp-per-node deterministic mean aggregation (near L2-BW floor)
// ---------------------------------------------------------------------------
__global__ void __launch_bounds__(256)
aggregate_kernel(const float* __restrict__ x) {
    int warp = (blockIdx.x * blockDim.x + threadIdx.x) >> 5;
    int lane = threadIdx.x & 31;
    if (warp >= NN) return;
    const int node = warp;

    int cnt = g_cnt[node];
    int n = min(cnt, MAXDEG);

    float sx = 0.0f, sy = 0.0f;
    const int4* csr4 = (const int4*)(g_csr + (size_t)node * MAXDEG);

    int i = 0;
    for (; i + 8 <= n; i += 8) {
        int4 a = csr4[(i >> 2) + 0];
        int4 c = csr4[(i >> 2) + 1];
        float2 v0 = *(const float2*)(x + (size_t)a.x * D + 2 * lane);
        float2 v1 = *(const float2*)(x + (size_t)a.y * D + 2 * lane);
        float2 v2 = *(const float2*)(x + (size_t)a.z * D + 2 * lane);
        float2 v3 = *(const float2*)(x + (size_t)a.w * D + 2 * lane);
        float2 v4 = *(const float2*)(x + (size_t)c.x * D + 2 * lane);
        float2 v5 = *(const float2*)(x + (size_t)c.y * D + 2 * lane);
        float2 v6 = *(const float2*)(x + (size_t)c.z * D + 2 * lane);
        float2 v7 = *(const float2*)(x + (size_t)c.w * D + 2 * lane);
        sx += ((v0.x + v1.x) + (v2.x + v3.x)) + ((v4.x + v5.x) + (v6.x + v7.x));
        sy += ((v0.y + v1.y) + (v2.y + v3.y)) + ((v4.y + v5.y) + (v6.y + v7.y));
    }
    for (; i < n; i++) {
        int src = g_csr[(size_t)node * MAXDEG + i];
        float2 v = *(const float2*)(x + (size_t)src * D + 2 * lane);
        sx += v.x; sy += v.y;
    }

    float inv = 1.0f / fmaxf((float)cnt, 1.0f);
    *(float2*)(g_agg + (size_t)node * D + 2 * lane) = make_float2(sx * inv, sy * inv);
}

// ---------------------------------------------------------------------------
// tf32 helpers (plain sm_80+ PTX — no arch-'a' features)
// ---------------------------------------------------------------------------
__device__ __forceinline__ uint32_t to_tf32(float f) {
    uint32_t r;
    asm("cvt.rna.tf32.f32 %0, %1;" : "=r"(r) : "f"(f));
    return r;
}
__device__ __forceinline__ void split_tf32(float f, uint32_t& hi, uint32_t& lo) {
    asm("cvt.rna.tf32.f32 %0, %1;" : "=r"(hi) : "f"(f));
    float r = f - __uint_as_float(hi);
    asm("cvt.rna.tf32.f32 %0, %1;" : "=r"(lo) : "f"(r));
}
__device__ __forceinline__ void mma_tf32(float* c, uint32_t a0, uint32_t a1,
                                         uint32_t a2, uint32_t a3,
                                         uint32_t b0, uint32_t b1) {
    asm volatile(
        "mma.sync.aligned.m16n8k8.row.col.f32.tf32.tf32.f32 "
        "{%0,%1,%2,%3}, {%4,%5,%6,%7}, {%8,%9}, {%0,%1,%2,%3};"
        : "+f"(c[0]), "+f"(c[1]), "+f"(c[2]), "+f"(c[3])
        : "r"(a0), "r"(a1), "r"(a2), "r"(a3), "r"(b0), "r"(b1));
}

// smem layout (floats)
#define SMF_H     0                         // h fp32        [64][HPAD]
#define SMF_WHI   (TM * HPAD)               // W hi tf32bits [64][HPAD]
#define SMF_WLO   (2 * TM * HPAD)           // W lo tf32bits [64][HPAD]
#define SMF_BIAS  (3 * TM * HPAD)
#define SMF_GAM   (SMF_BIAS + 64)
#define SMF_BET   (SMF_BIAS + 128)
#define SMF_TOTAL (SMF_BIAS + 192)

// ---------------------------------------------------------------------------
// Kernel 4: mma.sync tf32 fused GEMM (3xTF32) + bias + ReLU + LayerNorm.
// CTA = 64 nodes, 4 warps; warp w owns rows [16w,16w+16) x all 64 outputs.
// A = h rows (row-major m16k8 frags from smem fp32, split hi/lo in-loop),
// B = W (K-major [n][k] == col-major k8n8 frags), pre-split hi/lo in smem.
// ---------------------------------------------------------------------------
__global__ void __launch_bounds__(128, 2)
finalize_mma_kernel(const float* __restrict__ x,
                    const float* __restrict__ W,
                    const float* __restrict__ b,
                    const float* __restrict__ gamma,
                    const float* __restrict__ beta,
                    float* __restrict__ out) {
    extern __shared__ float sf[];
    float*    hs  = sf + SMF_H;
    uint32_t* whi = (uint32_t*)(sf + SMF_WHI);
    uint32_t* wlo = (uint32_t*)(sf + SMF_WLO);

    const int tid = threadIdx.x;
    const int wid = tid >> 5;
    const int lane = tid & 31;
    const int bnode0 = blockIdx.x * TM;

    if (tid < 64) {
        sf[SMF_BIAS + tid] = b[tid];
        sf[SMF_GAM + tid]  = gamma[tid];
        sf[SMF_BET + tid]  = beta[tid];
    }

    // --- stage h = [x | agg] fp32: 64 rows x 32 float4 chunks ---
    for (int t = tid; t < TM * 32; t += 128) {
        int row = t >> 5;
        int c   = t & 31;
        int gnode = min(bnode0 + row, NN - 1);
        float4 v;
        if (c < 16) v = ((const float4*)(x + (size_t)gnode * D))[c];
        else        v = ((const float4*)(g_agg + (size_t)gnode * D))[c - 16];
        *(float4*)&hs[row * HPAD + c * 4] = v;
    }
    // --- stage W split hi/lo (tf32 bit patterns): 64 rows x 32 chunks ---
    for (int t = tid; t < 64 * 32; t += 128) {
        int n = t >> 5;
        int c = t & 31;
        float4 v = ((const float4*)(W + n * 128))[c];
        uint4 h4, l4;
        split_tf32(v.x, h4.x, l4.x);
        split_tf32(v.y, h4.y, l4.y);
        split_tf32(v.z, h4.z, l4.z);
        split_tf32(v.w, h4.w, l4.w);
        *(uint4*)&whi[n * HPAD + c * 4] = h4;
        *(uint4*)&wlo[n * HPAD + c * 4] = l4;
    }
    __syncthreads();

    const int g = lane >> 2;        // group id (row within m16 / col within n8)
    const int t4 = lane & 3;        // thread in group (k index)
    const int band = wid * 16;

    float acc[32];                  // 8 n-tiles x 4 (c0..c3)
#pragma unroll
    for (int i = 0; i < 32; i++) acc[i] = 0.0f;

    const float*    arow0 = hs + (band + g) * HPAD;      // row g
    const float*    arow1 = hs + (band + g + 8) * HPAD;  // row g+8

#pragma unroll 2
    for (int ki = 0; ki < 16; ki++) {
        int k0 = ki * 8 + t4;
        // A fragment (m16k8 row-major): (g,k0) (g+8,k0) (g,k0+4) (g+8,k0+4)
        float fa0 = arow0[k0];
        float fa1 = arow1[k0];
        float fa2 = arow0[k0 + 4];
        float fa3 = arow1[k0 + 4];
        uint32_t ah0, al0, ah1, al1, ah2, al2, ah3, al3;
        split_tf32(fa0, ah0, al0);
        split_tf32(fa1, ah1, al1);
        split_tf32(fa2, ah2, al2);
        split_tf32(fa3, ah3, al3);

#pragma unroll
        for (int nt = 0; nt < 8; nt++) {
            // B fragment (k8n8 col-major): b0=(k0, n), b1=(k0+4, n), n = nt*8+g
            int boff = (nt * 8 + g) * HPAD + k0;
            uint32_t bh0 = whi[boff];
            uint32_t bh1 = whi[boff + 4];
            uint32_t bl0 = wlo[boff];
            uint32_t bl1 = wlo[boff + 4];
            float* c = acc + nt * 4;
            mma_tf32(c, ah0, ah1, ah2, ah3, bh0, bh1);   // hi*hi
            mma_tf32(c, ah0, ah1, ah2, ah3, bl0, bl1);   // hi*lo
            mma_tf32(c, al0, al1, al2, al3, bh0, bh1);   // lo*hi
        }
    }

    // --- epilogue: bias + ReLU + LayerNorm + store ---
    // thread owns cols {nt*8 + 2*t4, +1} for rows band+g and band+g+8
    float v0[16], v1[16];
    float s0 = 0.0f, s1 = 0.0f;
#pragma unroll
    for (int nt = 0; nt < 8; nt++) {
        int col = nt * 8 + 2 * t4;
        float2 bb = *(const float2*)&sf[SMF_BIAS + col];
        float a = fmaxf(acc[nt * 4 + 0] + bb.x, 0.0f);
        float bq = fmaxf(acc[nt * 4 + 1] + bb.y, 0.0f);
        float cq = fmaxf(acc[nt * 4 + 2] + bb.x, 0.0f);
        float dq = fmaxf(acc[nt * 4 + 3] + bb.y, 0.0f);
        v0[nt * 2] = a;  v0[nt * 2 + 1] = bq;
        v1[nt * 2] = cq; v1[nt * 2 + 1] = dq;
        s0 += a + bq;
        s1 += cq + dq;
    }
    s0 += __shfl_xor_sync(0xffffffffu, s0, 1);
    s0 += __shfl_xor_sync(0xffffffffu, s0, 2);
    s1 += __shfl_xor_sync(0xffffffffu, s1, 1);
    s1 += __shfl_xor_sync(0xffffffffu, s1, 2);
    float mu0 = s0 * (1.0f / D), mu1 = s1 * (1.0f / D);

    float ss0 = 0.0f, ss1 = 0.0f;
#pragma unroll
    for (int i = 0; i < 16; i++) {
        float d0 = v0[i] - mu0; ss0 += d0 * d0;
        float d1 = v1[i] - mu1; ss1 += d1 * d1;
    }
    ss0 += __shfl_xor_sync(0xffffffffu, ss0, 1);
    ss0 += __shfl_xor_sync(0xffffffffu, ss0, 2);
    ss1 += __shfl_xor_sync(0xffffffffu, ss1, 1);
    ss1 += __shfl_xor_sync(0xffffffffu, ss1, 2);
    float rs0 = rsqrtf(ss0 * (1.0f / D) + 1e-5f);
    float rs1 = rsqrtf(ss1 * (1.0f / D) + 1e-5f);

    int node0 = bnode0 + band + g;
    int node1 = node0 + 8;
#pragma unroll
    for (int nt = 0; nt < 8; nt++) {
        int col = nt * 8 + 2 * t4;
        float2 gg = *(const float2*)&sf[SMF_GAM + col];
        float2 be = *(const float2*)&sf[SMF_BET + col];
        if (node0 < NN) {
            float2 o;
            o.x = (v0[nt * 2]     - mu0) * rs0 * gg.x + be.x;
            o.y = (v0[nt * 2 + 1] - mu0) * rs0 * gg.y + be.y;
            *(float2*)(out + (size_t)node0 * D + col) = o;
        }
        if (node1 < NN) {
            float2 o;
            o.x = (v1[nt * 2]     - mu1) * rs1 * gg.x + be.x;
            o.y = (v1[nt * 2 + 1] - mu1) * rs1 * gg.y + be.y;
            *(float2*)(out + (size_t)node1 * D + col) = o;
        }
    }
}

// ---------------------------------------------------------------------------
extern "C" void kernel_launch(void* const* d_in, const int* in_sizes, int n_in,
                              void* d_out, int out_size) {
    const float* x     = (const float*)d_in[0];
    const int*   ei    = (const int*)d_in[1];
    const float* W     = (const float*)d_in[2];
    const float* b     = (const float*)d_in[3];
    const float* gamma = (const float*)d_in[4];
    const float* beta  = (const float*)d_in[5];
    float*       out   = (float*)d_out;

    (void)in_sizes; (void)n_in; (void)out_size;

    const int smem_bytes = SMF_TOTAL * sizeof(float);   // ~102 KB
    cudaFuncSetAttribute(finalize_mma_kernel,
                         cudaFuncAttributeMaxDynamicSharedMemorySize, smem_bytes);

    zero_cnt_kernel<<<(NN + 255) / 256, 256>>>();
    fill_kernel<<<(EE + 255) / 256, 256>>>(ei);
    aggregate_kernel<<<(NN * 32 + 255) / 256, 256>>>(x);
    finalize_mma_kernel<<<(NN + TM - 1) / TM, 128, smem_bytes>>>(x, W, b, gamma, beta, out);
}

// round 7
// speedup vs baseline: 2.4505x; 1.2795x over previous
#include <cuda_runtime.h>
#include <cstdint>

#define NN 100000
#define EE 1600000
#define D  64
#define MAXDEG 64    // avg degree = 16; P(deg > 64) ~ e^-126, plus runtime clamp
#define WPAD 132     // padded W row stride (uint32) — conflict-free B frag loads
#define NBANDS 6250  // 100000 / 16, exact
#define FGRID 296    // 2 CTAs/SM * 148 SMs

// Scratch (device globals: allocation-free per harness rules)
__device__ int      g_cnt[NN];
__device__ int      g_csr[(size_t)NN * MAXDEG];
__device__ float    g_agg[(size_t)NN * D];
__device__ uint32_t g_whi[64 * 128];     // W split: tf32 hi bits
__device__ uint32_t g_wlo[64 * 128];     // W split: tf32 lo bits

// ---------------------------------------------------------------------------
// tf32 helpers (plain sm_80+ PTX — no arch-'a' features)
// ---------------------------------------------------------------------------
__device__ __forceinline__ void split_tf32(float f, uint32_t& hi, uint32_t& lo) {
    asm("cvt.rna.tf32.f32 %0, %1;" : "=r"(hi) : "f"(f));
    float r = f - __uint_as_float(hi);
    asm("cvt.rna.tf32.f32 %0, %1;" : "=r"(lo) : "f"(r));
}
__device__ __forceinline__ void mma_tf32(float* c, uint32_t a0, uint32_t a1,
                                         uint32_t a2, uint32_t a3,
                                         uint32_t b0, uint32_t b1) {
    asm volatile(
        "mma.sync.aligned.m16n8k8.row.col.f32.tf32.tf32.f32 "
        "{%0,%1,%2,%3}, {%4,%5,%6,%7}, {%8,%9}, {%0,%1,%2,%3};"
        : "+f"(c[0]), "+f"(c[1]), "+f"(c[2]), "+f"(c[3])
        : "r"(a0), "r"(a1), "r"(a2), "r"(a3), "r"(b0), "r"(b1));
}

// ---------------------------------------------------------------------------
// Kernel 1: zero per-node counters
// ---------------------------------------------------------------------------
__global__ void zero_cnt_kernel() {
    int i = blockIdx.x * blockDim.x + threadIdx.x;
    if (i < NN) g_cnt[i] = 0;
}

// ---------------------------------------------------------------------------
// Kernel 1b: pre-split W into tf32 hi/lo (once; 8192 elements)
// ---------------------------------------------------------------------------
__global__ void prep_w_kernel(const float* __restrict__ W) {
    int i = blockIdx.x * blockDim.x + threadIdx.x;
    if (i < 64 * 128) {
        uint32_t hi, lo;
        split_tf32(W[i], hi, lo);
        g_whi[i] = hi;
        g_wlo[i] = lo;
    }
}

// ---------------------------------------------------------------------------
// Kernel 2: bucket edges into padded CSR. One int atomicAdd per edge.
// ---------------------------------------------------------------------------
__global__ void fill_kernel(const int* __restrict__ ei) {
    int e = blockIdx.x * blockDim.x + threadIdx.x;
    if (e >= EE) return;
    int dst = ei[e];
    int src = ei[EE + e];
    int pos = atomicAdd(g_cnt + dst, 1);
    if (pos < MAXDEG) g_csr[(size_t)dst * MAXDEG + pos] = src;
}

// ---------------------------------------------------------------------------
// Kernel 3: warp-per-node deterministic mean aggregation
// ---------------------------------------------------------------------------
__global__ void __launch_bounds__(256)
aggregate_kernel(const float* __restrict__ x) {
    int warp = (blockIdx.x * blockDim.x + threadIdx.x) >> 5;
    int lane = threadIdx.x & 31;
    if (warp >= NN) return;
    const int node = warp;

    int cnt = g_cnt[node];
    int n = min(cnt, MAXDEG);

    float sx = 0.0f, sy = 0.0f;
    const int4* csr4 = (const int4*)(g_csr + (size_t)node * MAXDEG);

    int i = 0;
    for (; i + 8 <= n; i += 8) {
        int4 a = csr4[(i >> 2) + 0];
        int4 c = csr4[(i >> 2) + 1];
        float2 v0 = *(const float2*)(x + (size_t)a.x * D + 2 * lane);
        float2 v1 = *(const float2*)(x + (size_t)a.y * D + 2 * lane);
        float2 v2 = *(const float2*)(x + (size_t)a.z * D + 2 * lane);
        float2 v3 = *(const float2*)(x + (size_t)a.w * D + 2 * lane);
        float2 v4 = *(const float2*)(x + (size_t)c.x * D + 2 * lane);
        float2 v5 = *(const float2*)(x + (size_t)c.y * D + 2 * lane);
        float2 v6 = *(const float2*)(x + (size_t)c.z * D + 2 * lane);
        float2 v7 = *(const float2*)(x + (size_t)c.w * D + 2 * lane);
        sx += ((v0.x + v1.x) + (v2.x + v3.x)) + ((v4.x + v5.x) + (v6.x + v7.x));
        sy += ((v0.y + v1.y) + (v2.y + v3.y)) + ((v4.y + v5.y) + (v6.y + v7.y));
    }
    for (; i < n; i++) {
        int src = g_csr[(size_t)node * MAXDEG + i];
        float2 v = *(const float2*)(x + (size_t)src * D + 2 * lane);
        sx += v.x; sy += v.y;
    }

    float inv = 1.0f / fmaxf((float)cnt, 1.0f);
    *(float2*)(g_agg + (size_t)node * D + 2 * lane) = make_float2(sx * inv, sy * inv);
}

// smem layout (uint32 units)
#define SMU_WHI   0
#define SMU_WLO   (64 * WPAD)
#define SMU_BIAS  (2 * 64 * WPAD)
#define SMU_GAM   (SMU_BIAS + 64)
#define SMU_BET   (SMU_BIAS + 128)
#define SMU_TOTAL (SMU_BIAS + 192)

// ---------------------------------------------------------------------------
// Kernel 4: persistent mma.sync tf32 (3xTF32) fused GEMM + bias + ReLU + LN.
// 296 CTAs x 8 warps. W hi/lo staged to smem once per CTA; warps then run
// autonomously over 16-node bands, prefetching A rows from global (x|agg)
// into registers. No per-band syncthreads, no h smem tile.
// ---------------------------------------------------------------------------
__global__ void __launch_bounds__(256, 2)
finalize_mma_kernel(const float* __restrict__ x,
                    const float* __restrict__ b,
                    const float* __restrict__ gamma,
                    const float* __restrict__ beta,
                    float* __restrict__ out) {
    extern __shared__ uint32_t su[];
    uint32_t* whi = su + SMU_WHI;           // [64][WPAD]
    uint32_t* wlo = su + SMU_WLO;           // [64][WPAD]
    float* bias = (float*)(su + SMU_BIAS);
    float* gam  = (float*)(su + SMU_GAM);
    float* bet  = (float*)(su + SMU_BET);

    const int tid  = threadIdx.x;
    const int wid  = tid >> 5;
    const int lane = tid & 31;

    // --- stage split W (once per CTA) ---
    for (int t = tid; t < 64 * 32; t += 256) {
        int n = t >> 5;
        int c = t & 31;
        uint4 h4 = *(const uint4*)(g_whi + n * 128 + c * 4);
        uint4 l4 = *(const uint4*)(g_wlo + n * 128 + c * 4);
        *(uint4*)(whi + n * WPAD + c * 4) = h4;
        *(uint4*)(wlo + n * WPAD + c * 4) = l4;
    }
    if (tid < 64) {
        bias[tid] = b[tid];
        gam[tid]  = gamma[tid];
        bet[tid]  = beta[tid];
    }
    __syncthreads();

    const int g  = lane >> 2;     // 0..7: row in m16 half / col in n8
    const int t4 = lane & 3;      // 0..3: k index within frag
    const int gwarp  = blockIdx.x * 8 + wid;
    const int nwarps = FGRID * 8;

    for (int band = gwarp; band < NBANDS; band += nwarps) {
        const int node0 = band * 16 + g;      // rows node0, node0+8 (always valid)
        const float* xr0 = x + (size_t)node0 * D;
        const float* xr1 = x + (size_t)(node0 + 8) * D;
        const float* ar0 = g_agg + (size_t)node0 * D;
        const float* ar1 = g_agg + (size_t)(node0 + 8) * D;

        float acc[32];
#pragma unroll
        for (int i = 0; i < 32; i++) acc[i] = 0.0f;

        // ---- half 1: k in [0,64) from x ----
        {
            float a0[8], a1[8], a2[8], a3[8];
#pragma unroll
            for (int ki = 0; ki < 8; ki++) {   // batched LDG for MLP
                int k0 = ki * 8 + t4;
                a0[ki] = __ldg(xr0 + k0);
                a1[ki] = __ldg(xr1 + k0);
                a2[ki] = __ldg(xr0 + k0 + 4);
                a3[ki] = __ldg(xr1 + k0 + 4);
            }
#pragma unroll
            for (int ki = 0; ki < 8; ki++) {
                int k0 = ki * 8 + t4;
                uint32_t ah0, al0, ah1, al1, ah2, al2, ah3, al3;
                split_tf32(a0[ki], ah0, al0);
                split_tf32(a1[ki], ah1, al1);
                split_tf32(a2[ki], ah2, al2);
                split_tf32(a3[ki], ah3, al3);
#pragma unroll
                for (int nt = 0; nt < 8; nt++) {
                    int boff = (nt * 8 + g) * WPAD + k0;
                    uint32_t bh0 = whi[boff];
                    uint32_t bh1 = whi[boff + 4];
                    uint32_t bl0 = wlo[boff];
                    uint32_t bl1 = wlo[boff + 4];
                    float* c = acc + nt * 4;
                    mma_tf32(c, ah0, ah1, ah2, ah3, bh0, bh1);
                    mma_tf32(c, ah0, ah1, ah2, ah3, bl0, bl1);
                    mma_tf32(c, al0, al1, al2, al3, bh0, bh1);
                }
            }
        }
        // ---- half 2: k in [64,128) from agg ----
        {
            float a0[8], a1[8], a2[8], a3[8];
#pragma unroll
            for (int ki = 0; ki < 8; ki++) {
                int kk = ki * 8 + t4;
                a0[ki] = __ldg(ar0 + kk);
                a1[ki] = __ldg(ar1 + kk);
                a2[ki] = __ldg(ar0 + kk + 4);
                a3[ki] = __ldg(ar1 + kk + 4);
            }
#pragma unroll
            for (int ki = 0; ki < 8; ki++) {
                int k0 = 64 + ki * 8 + t4;    // global k for B
                uint32_t ah0, al0, ah1, al1, ah2, al2, ah3, al3;
                split_tf32(a0[ki], ah0, al0);
                split_tf32(a1[ki], ah1, al1);
                split_tf32(a2[ki], ah2, al2);
                split_tf32(a3[ki], ah3, al3);
#pragma unroll
                for (int nt = 0; nt < 8; nt++) {
                    int boff = (nt * 8 + g) * WPAD + k0;
                    uint32_t bh0 = whi[boff];
                    uint32_t bh1 = whi[boff + 4];
                    uint32_t bl0 = wlo[boff];
                    uint32_t bl1 = wlo[boff + 4];
                    float* c = acc + nt * 4;
                    mma_tf32(c, ah0, ah1, ah2, ah3, bh0, bh1);
                    mma_tf32(c, ah0, ah1, ah2, ah3, bl0, bl1);
                    mma_tf32(c, al0, al1, al2, al3, bh0, bh1);
                }
            }
        }

        // ---- epilogue: bias + ReLU + LayerNorm + store ----
        float v0[16], v1[16];
        float s0 = 0.0f, s1 = 0.0f;
#pragma unroll
        for (int nt = 0; nt < 8; nt++) {
            int col = nt * 8 + 2 * t4;
            float2 bb = *(const float2*)&bias[col];
            float a = fmaxf(acc[nt * 4 + 0] + bb.x, 0.0f);
            float bq = fmaxf(acc[nt * 4 + 1] + bb.y, 0.0f);
            float cq = fmaxf(acc[nt * 4 + 2] + bb.x, 0.0f);
            float dq = fmaxf(acc[nt * 4 + 3] + bb.y, 0.0f);
            v0[nt * 2] = a;  v0[nt * 2 + 1] = bq;
            v1[nt * 2] = cq; v1[nt * 2 + 1] = dq;
            s0 += a + bq;
            s1 += cq + dq;
        }
        s0 += __shfl_xor_sync(0xffffffffu, s0, 1);
        s0 += __shfl_xor_sync(0xffffffffu, s0, 2);
        s1 += __shfl_xor_sync(0xffffffffu, s1, 1);
        s1 += __shfl_xor_sync(0xffffffffu, s1, 2);
        float mu0 = s0 * (1.0f / D), mu1 = s1 * (1.0f / D);

        float ss0 = 0.0f, ss1 = 0.0f;
#pragma unroll
        for (int i = 0; i < 16; i++) {
            float d0 = v0[i] - mu0; ss0 += d0 * d0;
            float d1 = v1[i] - mu1; ss1 += d1 * d1;
        }
        ss0 += __shfl_xor_sync(0xffffffffu, ss0, 1);
        ss0 += __shfl_xor_sync(0xffffffffu, ss0, 2);
        ss1 += __shfl_xor_sync(0xffffffffu, ss1, 1);
        ss1 += __shfl_xor_sync(0xffffffffu, ss1, 2);
        float rs0 = rsqrtf(ss0 * (1.0f / D) + 1e-5f);
        float rs1 = rsqrtf(ss1 * (1.0f / D) + 1e-5f);

        float* o0 = out + (size_t)node0 * D;
        float* o1 = out + (size_t)(node0 + 8) * D;
#pragma unroll
        for (int nt = 0; nt < 8; nt++) {
            int col = nt * 8 + 2 * t4;
            float2 gg = *(const float2*)&gam[col];
            float2 be = *(const float2*)&bet[col];
            float2 w0, w1;
            w0.x = (v0[nt * 2]     - mu0) * rs0 * gg.x + be.x;
            w0.y = (v0[nt * 2 + 1] - mu0) * rs0 * gg.y + be.y;
            w1.x = (v1[nt * 2]     - mu1) * rs1 * gg.x + be.x;
            w1.y = (v1[nt * 2 + 1] - mu1) * rs1 * gg.y + be.y;
            *(float2*)(o0 + col) = w0;
            *(float2*)(o1 + col) = w1;
        }
    }
}

// ---------------------------------------------------------------------------
extern "C" void kernel_launch(void* const* d_in, const int* in_sizes, int n_in,
                              void* d_out, int out_size) {
    const float* x     = (const float*)d_in[0];
    const int*   ei    = (const int*)d_in[1];
    const float* W     = (const float*)d_in[2];
    const float* b     = (const float*)d_in[3];
    const float* gamma = (const float*)d_in[4];
    const float* beta  = (const float*)d_in[5];
    float*       out   = (float*)d_out;

    (void)in_sizes; (void)n_in; (void)out_size;

    const int smem_bytes = SMU_TOTAL * sizeof(uint32_t);   // ~68.4 KB
    cudaFuncSetAttribute(finalize_mma_kernel,
                         cudaFuncAttributeMaxDynamicSharedMemorySize, smem_bytes);

    zero_cnt_kernel<<<(NN + 255) / 256, 256>>>();
    prep_w_kernel<<<(64 * 128 + 255) / 256, 256>>>(W);
    fill_kernel<<<(EE + 255) / 256, 256>>>(ei);
    aggregate_kernel<<<(NN * 32 + 255) / 256, 256>>>(x);
    finalize_mma_kernel<<<FGRID, 256, smem_bytes>>>(x, b, gamma, beta, out);
}

// round 8
// speedup vs baseline: 3.0167x; 1.2311x over previous
#include <cuda_runtime.h>
#include <cstdint>

#define NN 100000
#define EE 1600000
#define D  64
#define MAXDEG 64    // avg degree = 16; P(deg > 64) ~ e^-126, plus runtime clamp
#define NBANDS 6250  // 100000 / 16, exact
#define FGRID 296    // 2 CTAs/SM * 148 SMs
#define WSTRIDE 36   // uint2 per n-row in smem W tiles (conflict-free LDS.64)

// Scratch (device globals: allocation-free per harness rules)
__device__ int      g_cnt[NN];
__device__ int      g_csr[(size_t)NN * MAXDEG];
__device__ float    g_agg[(size_t)NN * D];
// W pre-packed bf16 fragments: index ((n*8 + chunk)*4 + t4) -> uint2 {b0, b1}
__device__ uint2    g_bhi[64 * 8 * 4];
__device__ uint2    g_blo[64 * 8 * 4];

// ---------------------------------------------------------------------------
// bf16 helpers (plain sm_80+ PTX)
// ---------------------------------------------------------------------------
__device__ __forceinline__ uint32_t pack_bf16(float lo, float hi) {
    uint32_t r;  // PTX cvt packs first source into upper half
    asm("cvt.rn.bf16x2.f32 %0, %1, %2;" : "=r"(r) : "f"(hi), "f"(lo));
    return r;
}
// split two floats into packed bf16 hi + packed bf16 residual
__device__ __forceinline__ void split2_bf16(float f0, float f1,
                                            uint32_t& hi, uint32_t& lo) {
    hi = pack_bf16(f0, f1);
    float h0 = __uint_as_float(hi << 16);
    float h1 = __uint_as_float(hi & 0xffff0000u);
    lo = pack_bf16(f0 - h0, f1 - h1);
}
__device__ __forceinline__ void mma_bf16(float* c, uint32_t a0, uint32_t a1,
                                         uint32_t a2, uint32_t a3,
                                         uint32_t b0, uint32_t b1) {
    asm volatile(
        "mma.sync.aligned.m16n8k16.row.col.f32.bf16.bf16.f32 "
        "{%0,%1,%2,%3}, {%4,%5,%6,%7}, {%8,%9}, {%0,%1,%2,%3};"
        : "+f"(c[0]), "+f"(c[1]), "+f"(c[2]), "+f"(c[3])
        : "r"(a0), "r"(a1), "r"(a2), "r"(a3), "r"(b0), "r"(b1));
}

// ---------------------------------------------------------------------------
// Kernel 1: setup = zero counters + pre-split/pack W fragments
// ---------------------------------------------------------------------------
__global__ void setup_kernel(const float* __restrict__ W) {
    int i = blockIdx.x * blockDim.x + threadIdx.x;
    if (i < NN) g_cnt[i] = 0;
    if (i < 64 * 8 * 4) {
        int t4 = i & 3;
        int c  = (i >> 2) & 7;
        int n  = i >> 5;
        const float* wr = W + n * 128 + c * 16;
        uint32_t h0, l0, h1, l1;
        split2_bf16(wr[2 * t4],     wr[2 * t4 + 1],     h0, l0);  // b0: k=2t4,2t4+1
        split2_bf16(wr[8 + 2 * t4], wr[8 + 2 * t4 + 1], h1, l1);  // b1: k=+8
        g_bhi[i] = make_uint2(h0, h1);
        g_blo[i] = make_uint2(l0, l1);
    }
}

// ---------------------------------------------------------------------------
// Kernel 2: bucket edges into padded CSR. One int atomicAdd per edge.
// ---------------------------------------------------------------------------
__global__ void fill_kernel(const int* __restrict__ ei) {
    int e = blockIdx.x * blockDim.x + threadIdx.x;
    if (e >= EE) return;
    int dst = ei[e];
    int src = ei[EE + e];
    int pos = atomicAdd(g_cnt + dst, 1);
    if (pos < MAXDEG) g_csr[(size_t)dst * MAXDEG + pos] = src;
}

// ---------------------------------------------------------------------------
// Kernel 3: mean aggregation, 2 nodes per warp (16 lanes x float4 per row).
// One LDG.128 instruction fetches neighbor rows for BOTH nodes (512B).
// ---------------------------------------------------------------------------
__global__ void __launch_bounds__(256)
aggregate_kernel(const float* __restrict__ x) {
    int warp = (blockIdx.x * blockDim.x + threadIdx.x) >> 5;
    int lane = threadIdx.x & 31;
    if (warp * 2 >= NN) return;
    const int node  = warp * 2 + (lane >> 4);
    const int lane16 = lane & 15;

    int cnt = g_cnt[node];
    int nloc = min(cnt, MAXDEG);
    int nmax = max(nloc, __shfl_xor_sync(0xffffffffu, nloc, 16));

    const int4* csr4 = (const int4*)(g_csr + (size_t)node * MAXDEG);
    const float4* x4 = (const float4*)x;

    float4 acc = make_float4(0.f, 0.f, 0.f, 0.f);
    for (int i = 0; i < nmax; i += 8) {
        int4 a = csr4[(i >> 2)];
        int4 c = csr4[(i >> 2) + 1];
        float4 v;
        if (i + 0 < nloc) { v = x4[(size_t)a.x * 16 + lane16]; acc.x += v.x; acc.y += v.y; acc.z += v.z; acc.w += v.w; }
        if (i + 1 < nloc) { v = x4[(size_t)a.y * 16 + lane16]; acc.x += v.x; acc.y += v.y; acc.z += v.z; acc.w += v.w; }
        if (i + 2 < nloc) { v = x4[(size_t)a.z * 16 + lane16]; acc.x += v.x; acc.y += v.y; acc.z += v.z; acc.w += v.w; }
        if (i + 3 < nloc) { v = x4[(size_t)a.w * 16 + lane16]; acc.x += v.x; acc.y += v.y; acc.z += v.z; acc.w += v.w; }
        if (i + 4 < nloc) { v = x4[(size_t)c.x * 16 + lane16]; acc.x += v.x; acc.y += v.y; acc.z += v.z; acc.w += v.w; }
        if (i + 5 < nloc) { v = x4[(size_t)c.y * 16 + lane16]; acc.x += v.x; acc.y += v.y; acc.z += v.z; acc.w += v.w; }
        if (i + 6 < nloc) { v = x4[(size_t)c.z * 16 + lane16]; acc.x += v.x; acc.y += v.y; acc.z += v.z; acc.w += v.w; }
        if (i + 7 < nloc) { v = x4[(size_t)c.w * 16 + lane16]; acc.x += v.x; acc.y += v.y; acc.z += v.z; acc.w += v.w; }
    }

    float inv = 1.0f / fmaxf((float)cnt, 1.0f);
    acc.x *= inv; acc.y *= inv; acc.z *= inv; acc.w *= inv;
    ((float4*)g_agg)[(size_t)node * 16 + lane16] = acc;
}

// smem layout (uint32 units)
#define SMU_WHI   0
#define SMU_WLO   (64 * WSTRIDE * 2)
#define SMU_BIAS  (2 * 64 * WSTRIDE * 2)
#define SMU_GAM   (SMU_BIAS + 64)
#define SMU_BET   (SMU_BIAS + 128)
#define SMU_TOTAL (SMU_BIAS + 192)

// ---------------------------------------------------------------------------
// Kernel 4: persistent mma.sync bf16 (3-way split) fused GEMM+bias+ReLU+LN.
// 296 CTAs x 8 warps; W fragments staged once per CTA; warps stream 16-node
// bands, A rows loaded from global (x | agg) and split in-register.
// ---------------------------------------------------------------------------
__global__ void __launch_bounds__(256, 2)
finalize_mma_kernel(const float* __restrict__ x,
                    const float* __restrict__ b,
                    const float* __restrict__ gamma,
                    const float* __restrict__ beta,
                    float* __restrict__ out) {
    extern __shared__ uint32_t su[];
    uint2* whi = (uint2*)(su + SMU_WHI);    // [64][WSTRIDE]
    uint2* wlo = (uint2*)(su + SMU_WLO);
    float* bias = (float*)(su + SMU_BIAS);
    float* gam  = (float*)(su + SMU_GAM);
    float* bet  = (float*)(su + SMU_BET);

    const int tid  = threadIdx.x;
    const int wid  = tid >> 5;
    const int lane = tid & 31;

    // stage packed W fragments (once per CTA)
    for (int t = tid; t < 64 * 32; t += 256) {
        int n = t >> 5;
        int s = t & 31;               // chunk*4 + t4
        whi[n * WSTRIDE + s] = g_bhi[n * 32 + s];
        wlo[n * WSTRIDE + s] = g_blo[n * 32 + s];
    }
    if (tid < 64) {
        bias[tid] = b[tid];
        gam[tid]  = gamma[tid];
        bet[tid]  = beta[tid];
    }
    __syncthreads();

    const int g  = lane >> 2;
    const int t4 = lane & 3;
    const int gwarp  = blockIdx.x * 8 + wid;
    const int nwarps = FGRID * 8;

    for (int band = gwarp; band < NBANDS; band += nwarps) {
        const int node0 = band * 16 + g;          // rows node0, node0+8
        const float* xr0 = x + (size_t)node0 * D;
        const float* xr1 = x + (size_t)(node0 + 8) * D;
        const float* ar0 = g_agg + (size_t)node0 * D;
        const float* ar1 = g_agg + (size_t)(node0 + 8) * D;

        float acc[32];
#pragma unroll
        for (int i = 0; i < 32; i++) acc[i] = 0.0f;

#pragma unroll
        for (int c = 0; c < 8; c++) {             // k16 chunk; 0-3 from x, 4-7 from agg
            const float* r0 = (c < 4) ? xr0 : ar0;
            const float* r1 = (c < 4) ? xr1 : ar1;
            int kb = (c & 3) * 16;
            float2 f00 = *(const float2*)(r0 + kb + 2 * t4);       // row g,   k lo
            float2 f01 = *(const float2*)(r0 + kb + 8 + 2 * t4);   // row g,   k hi
            float2 f10 = *(const float2*)(r1 + kb + 2 * t4);       // row g+8, k lo
            float2 f11 = *(const float2*)(r1 + kb + 8 + 2 * t4);   // row g+8, k hi

            uint32_t ah0, al0, ah1, al1, ah2, al2, ah3, al3;
            split2_bf16(f00.x, f00.y, ah0, al0);   // a0: row g,   cols 2t4..
            split2_bf16(f10.x, f10.y, ah1, al1);   // a1: row g+8
            split2_bf16(f01.x, f01.y, ah2, al2);   // a2: row g,   cols 8+2t4..
            split2_bf16(f11.x, f11.y, ah3, al3);   // a3: row g+8

#pragma unroll
            for (int nt = 0; nt < 8; nt++) {
                int off = (nt * 8 + g) * WSTRIDE + c * 4 + t4;
                uint2 bh = whi[off];
                uint2 bl = wlo[off];
                float* cc = acc + nt * 4;
                mma_bf16(cc, ah0, ah1, ah2, ah3, bh.x, bh.y);   // hi*hi
                mma_bf16(cc, ah0, ah1, ah2, ah3, bl.x, bl.y);   // hi*lo
                mma_bf16(cc, al0, al1, al2, al3, bh.x, bh.y);   // lo*hi
            }
        }

        // ---- epilogue: bias + ReLU + LayerNorm + store ----
        float v0[16], v1[16];
        float s0 = 0.0f, s1 = 0.0f;
#pragma unroll
        for (int nt = 0; nt < 8; nt++) {
            int col = nt * 8 + 2 * t4;
            float2 bb = *(const float2*)&bias[col];
            float a = fmaxf(acc[nt * 4 + 0] + bb.x, 0.0f);
            float bq = fmaxf(acc[nt * 4 + 1] + bb.y, 0.0f);
            float cq = fmaxf(acc[nt * 4 + 2] + bb.x, 0.0f);
            float dq = fmaxf(acc[nt * 4 + 3] + bb.y, 0.0f);
            v0[nt * 2] = a;  v0[nt * 2 + 1] = bq;
            v1[nt * 2] = cq; v1[nt * 2 + 1] = dq;
            s0 += a + bq;
            s1 += cq + dq;
        }
        s0 += __shfl_xor_sync(0xffffffffu, s0, 1);
        s0 += __shfl_xor_sync(0xffffffffu, s0, 2);
        s1 += __shfl_xor_sync(0xffffffffu, s1, 1);
        s1 += __shfl_xor_sync(0xffffffffu, s1, 2);
        float mu0 = s0 * (1.0f / D), mu1 = s1 * (1.0f / D);

        float ss0 = 0.0f, ss1 = 0.0f;
#pragma unroll
        for (int i = 0; i < 16; i++) {
            float d0 = v0[i] - mu0; ss0 += d0 * d0;
            float d1 = v1[i] - mu1; ss1 += d1 * d1;
        }
        ss0 += __shfl_xor_sync(0xffffffffu, ss0, 1);
        ss0 += __shfl_xor_sync(0xffffffffu, ss0, 2);
        ss1 += __shfl_xor_sync(0xffffffffu, ss1, 1);
        ss1 += __shfl_xor_sync(0xffffffffu, ss1, 2);
        float rs0 = rsqrtf(ss0 * (1.0f / D) + 1e-5f);
        float rs1 = rsqrtf(ss1 * (1.0f / D) + 1e-5f);

        float* o0 = out + (size_t)node0 * D;
        float* o1 = out + (size_t)(node0 + 8) * D;
#pragma unroll
        for (int nt = 0; nt < 8; nt++) {
            int col = nt * 8 + 2 * t4;
            float2 gg = *(const float2*)&gam[col];
            float2 be = *(const float2*)&bet[col];
            float2 w0, w1;
            w0.x = (v0[nt * 2]     - mu0) * rs0 * gg.x + be.x;
            w0.y = (v0[nt * 2 + 1] - mu0) * rs0 * gg.y + be.y;
            w1.x = (v1[nt * 2]     - mu1) * rs1 * gg.x + be.x;
            w1.y = (v1[nt * 2 + 1] - mu1) * rs1 * gg.y + be.y;
            *(float2*)(o0 + col) = w0;
            *(float2*)(o1 + col) = w1;
        }
    }
}

// ---------------------------------------------------------------------------
extern "C" void kernel_launch(void* const* d_in, const int* in_sizes, int n_in,
                              void* d_out, int out_size) {
    const float* x     = (const float*)d_in[0];
    const int*   ei    = (const int*)d_in[1];
    const float* W     = (const float*)d_in[2];
    const float* b     = (const float*)d_in[3];
    const float* gamma = (const float*)d_in[4];
    const float* beta  = (const float*)d_in[5];
    float*       out   = (float*)d_out;

    (void)in_sizes; (void)n_in; (void)out_size;

    const int smem_bytes = SMU_TOTAL * sizeof(uint32_t);   // ~37.6 KB
    cudaFuncSetAttribute(finalize_mma_kernel,
                         cudaFuncAttributeMaxDynamicSharedMemorySize, smem_bytes);

    setup_kernel<<<(NN + 255) / 256, 256>>>(W);
    fill_kernel<<<(EE + 255) / 256, 256>>>(ei);
    aggregate_kernel<<<(NN / 2 * 32 + 255) / 256, 256>>>(x);   // 2 nodes / warp
    finalize_mma_kernel<<<FGRID, 256, smem_bytes>>>(x, b, gamma, beta, out);
}